// round 2
// baseline (speedup 1.0000x reference)
#include <cuda_runtime.h>

#define B_ 2048
#define T_ 32
#define K_ 1024
#define D_ 256

#define BM 128
#define BN 128
#define BK 16

// Scratch (no allocations allowed in kernel_launch)
__device__ float g_csq[T_ * K_];   // 0.5 * ||c||^2
__device__ int   g_idx[B_ * T_];   // argmin indices

// ---------------------------------------------------------------------------
// Kernel 1: 0.5*||c_k||^2 per codebook row. One warp per row.
// ---------------------------------------------------------------------------
__global__ void csq_kernel(const float* __restrict__ cb) {
    int row  = blockIdx.x * 8 + (threadIdx.x >> 5);
    int lane = threadIdx.x & 31;
    if (row >= T_ * K_) return;
    const float4* p = (const float4*)(cb + (size_t)row * D_);
    float s = 0.f;
#pragma unroll
    for (int i = 0; i < 2; i++) {
        float4 v = p[lane + 32 * i];
        s += v.x * v.x + v.y * v.y + v.z * v.z + v.w * v.w;
    }
#pragma unroll
    for (int o = 16; o > 0; o >>= 1) s += __shfl_down_sync(0xffffffffu, s, o);
    if (lane == 0) g_csq[row] = 0.5f * s;
}

// ---------------------------------------------------------------------------
// Kernel 2: per (t, b-tile) compute scores s = 0.5*||c||^2 - x.c over all
// K=1024 codes, with a fused running argmin. Classic 128x128 SGEMM tiling,
// BK=16, 8x8 register microtiles, 256 threads.
// ---------------------------------------------------------------------------
__global__ __launch_bounds__(256)
void score_kernel(const float* __restrict__ x, const float* __restrict__ cb) {
    // Transposed shared tiles As[d][m], Bs[d][k]; stride 132 keeps float4
    // alignment (132*4 % 16 == 0) and limits store conflicts to 2-way.
    __shared__ float As[BK][BM + 4];
    __shared__ float Bs[BK][BN + 4];
    __shared__ float cs[BN];
    __shared__ float sval[BM][16];
    __shared__ int   sidx[BM][16];

    const int t   = blockIdx.y;
    const int bm0 = blockIdx.x * BM;
    const int tid = threadIdx.x;
    const int ty  = tid >> 4;   // 0..15 -> rows ty*8..ty*8+7
    const int tx  = tid & 15;   // 0..15 -> cols tx*8..tx*8+7

    const float* Cb = cb + (size_t)t * K_ * D_;

    float best[8];
    int   bidx[8];
#pragma unroll
    for (int i = 0; i < 8; i++) { best[i] = 3.4e38f; bidx[i] = 0; }

    for (int k0 = 0; k0 < K_; k0 += BN) {
        float acc[8][8];
#pragma unroll
        for (int i = 0; i < 8; i++)
#pragma unroll
            for (int j = 0; j < 8; j++) acc[i][j] = 0.f;

        for (int d0 = 0; d0 < D_; d0 += BK) {
            __syncthreads();   // protects As/Bs/cs against prior iteration readers
            if (d0 == 0 && tid < BN) cs[tid] = g_csq[t * K_ + k0 + tid];
            // Load 128x16 A tile and 128x16 B tile (512 float4 each half).
#pragma unroll
            for (int u = 0; u < 2; u++) {
                int q   = tid + u * 256;    // 0..511
                int row = q >> 2;           // 0..127
                int dc  = (q & 3) * 4;      // 0,4,8,12
                float4 v = *(const float4*)(x + ((size_t)(bm0 + row) * T_ + t) * D_ + d0 + dc);
                As[dc + 0][row] = v.x; As[dc + 1][row] = v.y;
                As[dc + 2][row] = v.z; As[dc + 3][row] = v.w;
                float4 w = *(const float4*)(Cb + (size_t)(k0 + row) * D_ + d0 + dc);
                Bs[dc + 0][row] = w.x; Bs[dc + 1][row] = w.y;
                Bs[dc + 2][row] = w.z; Bs[dc + 3][row] = w.w;
            }
            __syncthreads();
#pragma unroll
            for (int dd = 0; dd < BK; dd++) {
                float a[8], b[8];
                *(float4*)(a)     = *(const float4*)&As[dd][ty * 8];
                *(float4*)(a + 4) = *(const float4*)&As[dd][ty * 8 + 4];
                *(float4*)(b)     = *(const float4*)&Bs[dd][tx * 8];
                *(float4*)(b + 4) = *(const float4*)&Bs[dd][tx * 8 + 4];
#pragma unroll
                for (int i = 0; i < 8; i++)
#pragma unroll
                    for (int j = 0; j < 8; j++)
                        acc[i][j] = fmaf(a[i], b[j], acc[i][j]);
            }
        }

        // Running argmin update. k ascending + strict '<' => first occurrence.
#pragma unroll
        for (int j = 0; j < 8; j++) {
            int   k = k0 + tx * 8 + j;
            float h = cs[tx * 8 + j];
#pragma unroll
            for (int i = 0; i < 8; i++) {
                float s = h - acc[i][j];
                if (s < best[i]) { best[i] = s; bidx[i] = k; }
            }
        }
    }

    // Cross-thread reduction over the 16 column-owners per row.
    __syncthreads();
#pragma unroll
    for (int i = 0; i < 8; i++) {
        sval[ty * 8 + i][tx] = best[i];
        sidx[ty * 8 + i][tx] = bidx[i];
    }
    __syncthreads();
    if (tid < BM) {
        float bv = sval[tid][0];
        int   bi = sidx[tid][0];
#pragma unroll
        for (int c = 1; c < 16; c++) {
            float v  = sval[tid][c];
            int   ix = sidx[tid][c];
            if (v < bv || (v == bv && ix < bi)) { bv = v; bi = ix; }
        }
        g_idx[(size_t)(bm0 + tid) * T_ + t] = bi;
    }
}

// ---------------------------------------------------------------------------
// Kernel 3: gather winning codebook rows into out; optionally append idxes
// (as float) after the embed block if out_size includes them.
// ---------------------------------------------------------------------------
__global__ void gather_kernel(const float* __restrict__ cb,
                              float* __restrict__ out, int write_idx) {
    int bt  = blockIdx.x;          // bt = b*T + t
    int t   = bt & (T_ - 1);
    int idx = g_idx[bt];
    const float4* src = (const float4*)(cb + ((size_t)t * K_ + idx) * D_);
    float4*       dst = (float4*)(out + (size_t)bt * D_);
    dst[threadIdx.x] = src[threadIdx.x];   // 64 threads * 16B = 1KB row
    if (write_idx && threadIdx.x == 0)
        out[(size_t)B_ * T_ * D_ + bt] = (float)idx;
}

// ---------------------------------------------------------------------------
extern "C" void kernel_launch(void* const* d_in, const int* in_sizes, int n_in,
                              void* d_out, int out_size) {
    const float* x  = (const float*)d_in[0];   // input   [B, T, D]
    const float* cb = (const float*)d_in[1];   // codebook[T, K, D]
    float* out = (float*)d_out;

    csq_kernel<<<(T_ * K_) / 8, 256>>>(cb);

    dim3 grid(B_ / BM, T_);
    score_kernel<<<grid, 256>>>(x, cb);

    int write_idx = (out_size >= B_ * T_ * D_ + B_ * T_) ? 1 : 0;
    gather_kernel<<<B_ * T_, 64>>>(cb, out, write_idx);
}

// round 9
// speedup vs baseline: 1.9404x; 1.9404x over previous
#include <cuda_runtime.h>
#include <cuda_fp16.h>
#include <cstdint>

#define B_ 2048
#define T_ 32
#define K_ 1024
#define D_ 256
#define BM 128

// ---------------------------------------------------------------------------
// Scratch (static device arrays; no allocations allowed)
// ---------------------------------------------------------------------------
__device__ float  g_csq[T_ * K_];                // 0.5*||c||^2 (fp32 exact)
__device__ int    g_idx[B_ * T_];                // argmin indices
__device__ __half g_ch[(size_t)T_ * K_ * D_];    // codebook hi (fp16)
__device__ __half g_cl[(size_t)T_ * K_ * D_];    // codebook residual * 2048

// ---------------------------------------------------------------------------
// SMEM layout (bytes). Rows are 264 halfs = 528B; 132 words == 4 (mod 32), so
// the 32 (g,tig) fragment lanes hit banks (4g+tig) mod 32 = 0..31: conflict-free.
// ---------------------------------------------------------------------------
#define ASTR    528
#define AH_OFF  0
#define AL_OFF  67584
#define BH_OFF  135168
#define BL_OFF  168960
#define CSQ_OFF 202752
#define REDV_OFF 206848     // float sRedV[128][2]
#define REDI_OFF 207872     // int   sRedI[128][2]
#define SMEM_SZ  208896

__device__ __forceinline__ void mma16816(float* c, const uint32_t* a, const uint32_t* b) {
    asm volatile("mma.sync.aligned.m16n8k16.row.col.f32.f16.f16.f32 "
                 "{%0,%1,%2,%3}, {%4,%5,%6,%7}, {%8,%9}, {%0,%1,%2,%3};"
                 : "+f"(c[0]), "+f"(c[1]), "+f"(c[2]), "+f"(c[3])
                 : "r"(a[0]), "r"(a[1]), "r"(a[2]), "r"(a[3]), "r"(b[0]), "r"(b[1]));
}

// ---------------------------------------------------------------------------
// Kernel 1: codebook split (fp16 hi + 2048*residual) + 0.5*||c||^2. Warp/row.
// ---------------------------------------------------------------------------
__global__ void split_kernel(const float* __restrict__ cb) {
    int row  = blockIdx.x * 8 + (threadIdx.x >> 5);
    int lane = threadIdx.x & 31;
    const float4* p = (const float4*)(cb + (size_t)row * D_);
    float4 v0 = p[lane * 2 + 0];
    float4 v1 = p[lane * 2 + 1];
    float a[8] = {v0.x, v0.y, v0.z, v0.w, v1.x, v1.y, v1.z, v1.w};
    float s = 0.f;
#pragma unroll
    for (int i = 0; i < 8; i++) s += a[i] * a[i];
#pragma unroll
    for (int o = 16; o > 0; o >>= 1) s += __shfl_xor_sync(0xffffffffu, s, o);
    if (lane == 0) g_csq[row] = 0.5f * s;

    __half h[8], l[8];
#pragma unroll
    for (int i = 0; i < 8; i++) {
        h[i] = __float2half_rn(a[i]);
        l[i] = __float2half_rn((a[i] - __half2float(h[i])) * 2048.f);
    }
    uint4 uh, ul;
    uh.x = ((uint32_t)__half_as_ushort(h[0])) | ((uint32_t)__half_as_ushort(h[1]) << 16);
    uh.y = ((uint32_t)__half_as_ushort(h[2])) | ((uint32_t)__half_as_ushort(h[3]) << 16);
    uh.z = ((uint32_t)__half_as_ushort(h[4])) | ((uint32_t)__half_as_ushort(h[5]) << 16);
    uh.w = ((uint32_t)__half_as_ushort(h[6])) | ((uint32_t)__half_as_ushort(h[7]) << 16);
    ul.x = ((uint32_t)__half_as_ushort(l[0])) | ((uint32_t)__half_as_ushort(l[1]) << 16);
    ul.y = ((uint32_t)__half_as_ushort(l[2])) | ((uint32_t)__half_as_ushort(l[3]) << 16);
    ul.z = ((uint32_t)__half_as_ushort(l[4])) | ((uint32_t)__half_as_ushort(l[5]) << 16);
    ul.w = ((uint32_t)__half_as_ushort(l[6])) | ((uint32_t)__half_as_ushort(l[7]) << 16);
    *(uint4*)(g_ch + (size_t)row * D_ + lane * 8) = uh;
    *(uint4*)(g_cl + (size_t)row * D_ + lane * 8) = ul;
}

// ---------------------------------------------------------------------------
// Kernel 2: HMMA split-fp16 GEMM + fused argmin. Fragments via plain LDS.32
// per PTX mma fragment tables. Grid (B/128, T), 256 threads = 8 warps (4x2),
// warp tile 32x32. Final argmin combines BOTH warps sharing each row block
// (wn=0 covers k%64<32, wn=32 covers k%64>=32) via SMEM -- the missing step
// that broke Rounds 4/6.
// ---------------------------------------------------------------------------
__global__ __launch_bounds__(256, 1)
void mma_kernel(const float* __restrict__ x) {
    extern __shared__ char smem[];
    const int tid  = threadIdx.x;
    const int lane = tid & 31;
    const int wid  = tid >> 5;
    const int t    = blockIdx.y;
    const int bm0  = blockIdx.x * BM;
    const int wm   = (wid >> 1) * 32;   // warp row offset in CTA tile
    const int wn   = (wid & 1) * 32;    // warp col offset in 64-wide n-tile
    const int g    = lane >> 2;         // groupID (fragment row / B col)
    const int tig  = lane & 3;          // thread-in-group (k pairs)
    float* sCsq  = (float*)(smem + CSQ_OFF);
    float* sRedV = (float*)(smem + REDV_OFF);
    int*   sRedI = (int*)(smem + REDI_OFF);

    // ---- Prologue: stage x tile split to (hi, lo*2048) fp16; preload csq --
#pragma unroll
    for (int it = 0; it < 32; it++) {
        int q   = tid + it * 256;          // 8192 float4 loads
        int row = q >> 6;
        int c4  = q & 63;
        float4 v = *(const float4*)(x + ((size_t)(bm0 + row) * T_ + t) * D_ + c4 * 4);
        float a4[4] = {v.x, v.y, v.z, v.w};
        __half h4[4], l4[4];
#pragma unroll
        for (int i = 0; i < 4; i++) {
            h4[i] = __float2half_rn(a4[i]);
            l4[i] = __float2half_rn((a4[i] - __half2float(h4[i])) * 2048.f);
        }
        uint2 uh, ul;
        uh.x = ((uint32_t)__half_as_ushort(h4[0])) | ((uint32_t)__half_as_ushort(h4[1]) << 16);
        uh.y = ((uint32_t)__half_as_ushort(h4[2])) | ((uint32_t)__half_as_ushort(h4[3]) << 16);
        ul.x = ((uint32_t)__half_as_ushort(l4[0])) | ((uint32_t)__half_as_ushort(l4[1]) << 16);
        ul.y = ((uint32_t)__half_as_ushort(l4[2])) | ((uint32_t)__half_as_ushort(l4[3]) << 16);
        *(uint2*)(smem + AH_OFF + row * ASTR + c4 * 8) = uh;
        *(uint2*)(smem + AL_OFF + row * ASTR + c4 * 8) = ul;
    }
#pragma unroll
    for (int i = 0; i < 4; i++) sCsq[tid + i * 256] = g_csq[t * K_ + tid + i * 256];

    // Per-thread fragment byte offsets (within each A/B array).
    const uint32_t aBase = (uint32_t)(wm + g) * ASTR + (uint32_t)tig * 4;
    const uint32_t bBase = (uint32_t)(wn + g) * ASTR + (uint32_t)tig * 4;

    float best[4];
    int   bidx[4];
#pragma unroll
    for (int i = 0; i < 4; i++) { best[i] = 3.4e38f; bidx[i] = 0; }

    const float inv  = 1.f / 2048.f;
    const float inv2 = inv * inv;

    for (int nt = 0; nt < 16; nt++) {
        const int n0 = nt * 64;
        __syncthreads();   // prev k-loop done (B reuse) / prologue done (nt=0)

        // ---- Load B tile: 64 codes x 256 d, hi + lo ----
#pragma unroll
        for (int it = 0; it < 16; it++) {
            int q   = tid + it * 256;       // 4096 uint4
            int arr = q >> 11;
            int e   = q & 2047;
            int n   = e >> 5;
            int ck  = e & 31;
            const __half* src = (arr ? g_cl : g_ch)
                              + ((size_t)t * K_ + n0 + n) * D_ + ck * 8;
            *(uint4*)(smem + (arr ? BL_OFF : BH_OFF) + n * ASTR + ck * 16) =
                *(const uint4*)src;
        }
        __syncthreads();

        // ---- K-loop: C1 = xh*ch, C2 = xh*cl + xl*ch, C3 = xl*cl ----
        float C1[2][4][4], C2[2][4][4], C3[2][4][4];
#pragma unroll
        for (int mb = 0; mb < 2; mb++)
#pragma unroll
            for (int nb = 0; nb < 4; nb++)
#pragma unroll
                for (int r = 0; r < 4; r++) {
                    C1[mb][nb][r] = 0.f; C2[mb][nb][r] = 0.f; C3[mb][nb][r] = 0.f;
                }

#pragma unroll 2
        for (int kk = 0; kk < D_; kk += 16) {
            uint32_t ah[2][4], al[2][4], bh[4][2], bl[4][2];
#pragma unroll
            for (int mb = 0; mb < 2; mb++) {
                uint32_t a = aBase + (uint32_t)mb * (16 * ASTR) + (uint32_t)kk * 2;
                // a0:(g,k) a1:(g+8,k) a2:(g,k+8) a3:(g+8,k+8)
                ah[mb][0] = *(const uint32_t*)(smem + AH_OFF + a);
                ah[mb][1] = *(const uint32_t*)(smem + AH_OFF + a + 8 * ASTR);
                ah[mb][2] = *(const uint32_t*)(smem + AH_OFF + a + 16);
                ah[mb][3] = *(const uint32_t*)(smem + AH_OFF + a + 8 * ASTR + 16);
                al[mb][0] = *(const uint32_t*)(smem + AL_OFF + a);
                al[mb][1] = *(const uint32_t*)(smem + AL_OFF + a + 8 * ASTR);
                al[mb][2] = *(const uint32_t*)(smem + AL_OFF + a + 16);
                al[mb][3] = *(const uint32_t*)(smem + AL_OFF + a + 8 * ASTR + 16);
            }
#pragma unroll
            for (int nb = 0; nb < 4; nb++) {
                uint32_t b = bBase + (uint32_t)nb * (8 * ASTR) + (uint32_t)kk * 2;
                // b0:(k, n=g) b1:(k+8, n=g)
                bh[nb][0] = *(const uint32_t*)(smem + BH_OFF + b);
                bh[nb][1] = *(const uint32_t*)(smem + BH_OFF + b + 16);
                bl[nb][0] = *(const uint32_t*)(smem + BL_OFF + b);
                bl[nb][1] = *(const uint32_t*)(smem + BL_OFF + b + 16);
            }
#pragma unroll
            for (int mb = 0; mb < 2; mb++)
#pragma unroll
                for (int nb = 0; nb < 4; nb++) {
                    mma16816(C1[mb][nb], ah[mb], bh[nb]);
                    mma16816(C2[mb][nb], ah[mb], bl[nb]);
                    mma16816(C2[mb][nb], al[mb], bh[nb]);
                    mma16816(C3[mb][nb], al[mb], bl[nb]);
                }
        }

        // ---- Fused argmin over this tile (registers + smem csq) ----
        // C frag: c0:(g, c) c1:(g, c+1) c2:(g+8, c) c3:(g+8, c+1), c = tig*2.
#pragma unroll
        for (int nb = 0; nb < 4; nb++) {
            int gcol = n0 + wn + nb * 8 + tig * 2;
            float cs0 = sCsq[gcol];
            float cs1 = sCsq[gcol + 1];
#pragma unroll
            for (int mb = 0; mb < 2; mb++) {
                float s0 = cs0 - (C1[mb][nb][0] + C2[mb][nb][0] * inv + C3[mb][nb][0] * inv2);
                float s1 = cs1 - (C1[mb][nb][1] + C2[mb][nb][1] * inv + C3[mb][nb][1] * inv2);
                float s2 = cs0 - (C1[mb][nb][2] + C2[mb][nb][2] * inv + C3[mb][nb][2] * inv2);
                float s3 = cs1 - (C1[mb][nb][3] + C2[mb][nb][3] * inv + C3[mb][nb][3] * inv2);
                int u = mb * 2;
                if (s0 < best[u])     { best[u]     = s0; bidx[u]     = gcol; }
                if (s1 < best[u])     { best[u]     = s1; bidx[u]     = gcol + 1; }
                if (s2 < best[u + 1]) { best[u + 1] = s2; bidx[u + 1] = gcol; }
                if (s3 < best[u + 1]) { best[u + 1] = s3; bidx[u + 1] = gcol + 1; }
            }
        }
    }

    // ---- Quad reduction (tig lanes hold different cols of same rows) ----
#pragma unroll
    for (int i = 0; i < 4; i++) {
#pragma unroll
        for (int off = 1; off <= 2; off <<= 1) {
            float v  = __shfl_xor_sync(0xffffffffu, best[i], off);
            int   ix = __shfl_xor_sync(0xffffffffu, bidx[i], off);
            if (v < best[i] || (v == best[i] && ix < bidx[i])) {
                best[i] = v; bidx[i] = ix;
            }
        }
    }

    // ---- Cross-warp combine: warps (wm, wn=0) and (wm, wn=32) share rows ---
    if (tig == 0) {
        int half = wn >> 5;   // 0 or 1
#pragma unroll
        for (int mb = 0; mb < 2; mb++)
#pragma unroll
            for (int h = 0; h < 2; h++) {
                int r = wm + mb * 16 + h * 8 + g;
                sRedV[r * 2 + half] = best[mb * 2 + h];
                sRedI[r * 2 + half] = bidx[mb * 2 + h];
            }
    }
    __syncthreads();
    if (tid < BM) {
        float v0 = sRedV[tid * 2],     v1 = sRedV[tid * 2 + 1];
        int   i0 = sRedI[tid * 2],     i1 = sRedI[tid * 2 + 1];
        int   win = (v1 < v0 || (v1 == v0 && i1 < i0)) ? i1 : i0;
        g_idx[(size_t)(bm0 + tid) * T_ + t] = win;
    }
}

// ---------------------------------------------------------------------------
// Kernel 3: gather winning codebook rows; append idxes (as float) if present.
// ---------------------------------------------------------------------------
__global__ void gather_kernel(const float* __restrict__ cb,
                              float* __restrict__ out, int write_idx) {
    int bt  = blockIdx.x;
    int t   = bt & (T_ - 1);
    int idx = g_idx[bt];
    const float4* src = (const float4*)(cb + ((size_t)t * K_ + idx) * D_);
    float4*       dst = (float4*)(out + (size_t)bt * D_);
    dst[threadIdx.x] = src[threadIdx.x];
    if (write_idx && threadIdx.x == 0)
        out[(size_t)B_ * T_ * D_ + bt] = (float)idx;
}

// ---------------------------------------------------------------------------
extern "C" void kernel_launch(void* const* d_in, const int* in_sizes, int n_in,
                              void* d_out, int out_size) {
    const float* x  = (const float*)d_in[0];   // [B, T, D] fp32
    const float* cb = (const float*)d_in[1];   // [T, K, D] fp32
    float* out = (float*)d_out;

    split_kernel<<<(T_ * K_) / 8, 256>>>(cb);

    cudaFuncSetAttribute(mma_kernel, cudaFuncAttributeMaxDynamicSharedMemorySize, SMEM_SZ);
    dim3 grid(B_ / BM, T_);
    mma_kernel<<<grid, 256, SMEM_SZ>>>(x);

    int write_idx = (out_size >= B_ * T_ * D_ + B_ * T_) ? 1 : 0;
    gather_kernel<<<B_ * T_, 64>>>(cb, out, write_idx);
}

// round 12
// speedup vs baseline: 2.2715x; 1.1707x over previous
#include <cuda_runtime.h>
#include <cuda_fp16.h>
#include <cstdint>

#define B_ 2048
#define T_ 32
#define K_ 1024
#define D_ 256
#define BM 128

// ---------------------------------------------------------------------------
// Scratch (static device arrays; no allocations allowed)
// ---------------------------------------------------------------------------
__device__ float  g_csq[T_ * K_];                // 0.5*||c||^2 (fp32 exact)
__device__ int    g_idx[B_ * T_];                // argmin indices
__device__ __half g_ch[(size_t)T_ * K_ * D_];    // codebook hi (fp16)
__device__ __half g_cl[(size_t)T_ * K_ * D_];    // codebook residual * 2048

// ---------------------------------------------------------------------------
// SMEM layout (bytes). Rows are 264 halfs = 528B; 132 words == 4 (mod 32), so
// the 32 (g,tig) fragment lanes hit banks (4g+tig) mod 32 = 0..31: conflict-free.
// ---------------------------------------------------------------------------
#define ASTR    528
#define AH_OFF  0
#define AL_OFF  67584
#define BH_OFF  135168
#define BL_OFF  168960
#define CSQ_OFF 202752
#define REDV_OFF 206848     // float sRedV[128][2]
#define REDI_OFF 207872     // int   sRedI[128][2]
#define SMEM_SZ  208896

__device__ __forceinline__ void mma16816(float* c, const uint32_t* a, const uint32_t* b) {
    asm volatile("mma.sync.aligned.m16n8k16.row.col.f32.f16.f16.f32 "
                 "{%0,%1,%2,%3}, {%4,%5,%6,%7}, {%8,%9}, {%0,%1,%2,%3};"
                 : "+f"(c[0]), "+f"(c[1]), "+f"(c[2]), "+f"(c[3])
                 : "r"(a[0]), "r"(a[1]), "r"(a[2]), "r"(a[3]), "r"(b[0]), "r"(b[1]));
}

// ---------------------------------------------------------------------------
// Kernel 1: codebook split (fp16 hi + 2048*residual) + 0.5*||c||^2. Warp/row.
// ---------------------------------------------------------------------------
__global__ void split_kernel(const float* __restrict__ cb) {
    int row  = blockIdx.x * 8 + (threadIdx.x >> 5);
    int lane = threadIdx.x & 31;
    const float4* p = (const float4*)(cb + (size_t)row * D_);
    float4 v0 = p[lane * 2 + 0];
    float4 v1 = p[lane * 2 + 1];
    float a[8] = {v0.x, v0.y, v0.z, v0.w, v1.x, v1.y, v1.z, v1.w};
    float s = 0.f;
#pragma unroll
    for (int i = 0; i < 8; i++) s += a[i] * a[i];
#pragma unroll
    for (int o = 16; o > 0; o >>= 1) s += __shfl_xor_sync(0xffffffffu, s, o);
    if (lane == 0) g_csq[row] = 0.5f * s;

    __half h[8], l[8];
#pragma unroll
    for (int i = 0; i < 8; i++) {
        h[i] = __float2half_rn(a[i]);
        l[i] = __float2half_rn((a[i] - __half2float(h[i])) * 2048.f);
    }
    uint4 uh, ul;
    uh.x = ((uint32_t)__half_as_ushort(h[0])) | ((uint32_t)__half_as_ushort(h[1]) << 16);
    uh.y = ((uint32_t)__half_as_ushort(h[2])) | ((uint32_t)__half_as_ushort(h[3]) << 16);
    uh.z = ((uint32_t)__half_as_ushort(h[4])) | ((uint32_t)__half_as_ushort(h[5]) << 16);
    uh.w = ((uint32_t)__half_as_ushort(h[6])) | ((uint32_t)__half_as_ushort(h[7]) << 16);
    ul.x = ((uint32_t)__half_as_ushort(l[0])) | ((uint32_t)__half_as_ushort(l[1]) << 16);
    ul.y = ((uint32_t)__half_as_ushort(l[2])) | ((uint32_t)__half_as_ushort(l[3]) << 16);
    ul.z = ((uint32_t)__half_as_ushort(l[4])) | ((uint32_t)__half_as_ushort(l[5]) << 16);
    ul.w = ((uint32_t)__half_as_ushort(l[6])) | ((uint32_t)__half_as_ushort(l[7]) << 16);
    *(uint4*)(g_ch + (size_t)row * D_ + lane * 8) = uh;
    *(uint4*)(g_cl + (size_t)row * D_ + lane * 8) = ul;
}

// ---------------------------------------------------------------------------
// Kernel 2: HMMA split-fp16 GEMM + fused argmin, 3-MMA form:
//   x.c ~= xh*ch + (xh*cl + xl*ch)/2048      (xl*cl/2048^2 term dropped;
//   bounded by ~1.5e-5 per score vs top-2 gaps >> 1e-3)
// Fragments via plain LDS.32 per PTX mma fragment tables. Grid (B/128, T),
// 256 threads = 8 warps (4x2), warp tile 32x32; cross-warp argmin via SMEM.
// ---------------------------------------------------------------------------
__global__ __launch_bounds__(256, 1)
void mma_kernel(const float* __restrict__ x) {
    extern __shared__ char smem[];
    const int tid  = threadIdx.x;
    const int lane = tid & 31;
    const int wid  = tid >> 5;
    const int t    = blockIdx.y;
    const int bm0  = blockIdx.x * BM;
    const int wm   = (wid >> 1) * 32;   // warp row offset in CTA tile
    const int wn   = (wid & 1) * 32;    // warp col offset in 64-wide n-tile
    const int g    = lane >> 2;         // groupID (fragment row / B col)
    const int tig  = lane & 3;          // thread-in-group (k pairs)
    float* sCsq  = (float*)(smem + CSQ_OFF);
    float* sRedV = (float*)(smem + REDV_OFF);
    int*   sRedI = (int*)(smem + REDI_OFF);

    // ---- Prologue: stage x tile split to (hi, lo*2048) fp16; preload csq --
#pragma unroll
    for (int it = 0; it < 32; it++) {
        int q   = tid + it * 256;          // 8192 float4 loads
        int row = q >> 6;
        int c4  = q & 63;
        float4 v = *(const float4*)(x + ((size_t)(bm0 + row) * T_ + t) * D_ + c4 * 4);
        float a4[4] = {v.x, v.y, v.z, v.w};
        __half h4[4], l4[4];
#pragma unroll
        for (int i = 0; i < 4; i++) {
            h4[i] = __float2half_rn(a4[i]);
            l4[i] = __float2half_rn((a4[i] - __half2float(h4[i])) * 2048.f);
        }
        uint2 uh, ul;
        uh.x = ((uint32_t)__half_as_ushort(h4[0])) | ((uint32_t)__half_as_ushort(h4[1]) << 16);
        uh.y = ((uint32_t)__half_as_ushort(h4[2])) | ((uint32_t)__half_as_ushort(h4[3]) << 16);
        ul.x = ((uint32_t)__half_as_ushort(l4[0])) | ((uint32_t)__half_as_ushort(l4[1]) << 16);
        ul.y = ((uint32_t)__half_as_ushort(l4[2])) | ((uint32_t)__half_as_ushort(l4[3]) << 16);
        *(uint2*)(smem + AH_OFF + row * ASTR + c4 * 8) = uh;
        *(uint2*)(smem + AL_OFF + row * ASTR + c4 * 8) = ul;
    }
#pragma unroll
    for (int i = 0; i < 4; i++) sCsq[tid + i * 256] = g_csq[t * K_ + tid + i * 256];

    // Per-thread fragment byte offsets (within each A/B array).
    const uint32_t aBase = (uint32_t)(wm + g) * ASTR + (uint32_t)tig * 4;
    const uint32_t bBase = (uint32_t)(wn + g) * ASTR + (uint32_t)tig * 4;

    float best[4];
    int   bidx[4];
#pragma unroll
    for (int i = 0; i < 4; i++) { best[i] = 3.4e38f; bidx[i] = 0; }

    const float inv = 1.f / 2048.f;

    for (int nt = 0; nt < 16; nt++) {
        const int n0 = nt * 64;
        __syncthreads();   // prev k-loop done (B reuse) / prologue done (nt=0)

        // ---- Load B tile: 64 codes x 256 d, hi + lo ----
#pragma unroll
        for (int it = 0; it < 16; it++) {
            int q   = tid + it * 256;       // 4096 uint4
            int arr = q >> 11;
            int e   = q & 2047;
            int n   = e >> 5;
            int ck  = e & 31;
            const __half* src = (arr ? g_cl : g_ch)
                              + ((size_t)t * K_ + n0 + n) * D_ + ck * 8;
            *(uint4*)(smem + (arr ? BL_OFF : BH_OFF) + n * ASTR + ck * 16) =
                *(const uint4*)src;
        }
        __syncthreads();

        // ---- K-loop: C1 = xh*ch ; C2 = xh*cl + xl*ch ----
        float C1[2][4][4], C2[2][4][4];
#pragma unroll
        for (int mb = 0; mb < 2; mb++)
#pragma unroll
            for (int nb = 0; nb < 4; nb++)
#pragma unroll
                for (int r = 0; r < 4; r++) { C1[mb][nb][r] = 0.f; C2[mb][nb][r] = 0.f; }

#pragma unroll 2
        for (int kk = 0; kk < D_; kk += 16) {
            uint32_t ah[2][4], al[2][4], bh[4][2], bl[4][2];
#pragma unroll
            for (int mb = 0; mb < 2; mb++) {
                uint32_t a = aBase + (uint32_t)mb * (16 * ASTR) + (uint32_t)kk * 2;
                // a0:(g,k) a1:(g+8,k) a2:(g,k+8) a3:(g+8,k+8)
                ah[mb][0] = *(const uint32_t*)(smem + AH_OFF + a);
                ah[mb][1] = *(const uint32_t*)(smem + AH_OFF + a + 8 * ASTR);
                ah[mb][2] = *(const uint32_t*)(smem + AH_OFF + a + 16);
                ah[mb][3] = *(const uint32_t*)(smem + AH_OFF + a + 8 * ASTR + 16);
                al[mb][0] = *(const uint32_t*)(smem + AL_OFF + a);
                al[mb][1] = *(const uint32_t*)(smem + AL_OFF + a + 8 * ASTR);
                al[mb][2] = *(const uint32_t*)(smem + AL_OFF + a + 16);
                al[mb][3] = *(const uint32_t*)(smem + AL_OFF + a + 8 * ASTR + 16);
            }
#pragma unroll
            for (int nb = 0; nb < 4; nb++) {
                uint32_t b = bBase + (uint32_t)nb * (8 * ASTR) + (uint32_t)kk * 2;
                // b0:(k, n=g) b1:(k+8, n=g)
                bh[nb][0] = *(const uint32_t*)(smem + BH_OFF + b);
                bh[nb][1] = *(const uint32_t*)(smem + BH_OFF + b + 16);
                bl[nb][0] = *(const uint32_t*)(smem + BL_OFF + b);
                bl[nb][1] = *(const uint32_t*)(smem + BL_OFF + b + 16);
            }
#pragma unroll
            for (int mb = 0; mb < 2; mb++)
#pragma unroll
                for (int nb = 0; nb < 4; nb++) {
                    mma16816(C1[mb][nb], ah[mb], bh[nb]);
                    mma16816(C2[mb][nb], ah[mb], bl[nb]);
                    mma16816(C2[mb][nb], al[mb], bh[nb]);
                }
        }

        // ---- Fused argmin over this tile (registers + smem csq) ----
        // C frag: c0:(g, c) c1:(g, c+1) c2:(g+8, c) c3:(g+8, c+1), c = tig*2.
#pragma unroll
        for (int nb = 0; nb < 4; nb++) {
            int gcol = n0 + wn + nb * 8 + tig * 2;
            float cs0 = sCsq[gcol];
            float cs1 = sCsq[gcol + 1];
#pragma unroll
            for (int mb = 0; mb < 2; mb++) {
                float s0 = cs0 - (C1[mb][nb][0] + C2[mb][nb][0] * inv);
                float s1 = cs1 - (C1[mb][nb][1] + C2[mb][nb][1] * inv);
                float s2 = cs0 - (C1[mb][nb][2] + C2[mb][nb][2] * inv);
                float s3 = cs1 - (C1[mb][nb][3] + C2[mb][nb][3] * inv);
                int u = mb * 2;
                if (s0 < best[u])     { best[u]     = s0; bidx[u]     = gcol; }
                if (s1 < best[u])     { best[u]     = s1; bidx[u]     = gcol + 1; }
                if (s2 < best[u + 1]) { best[u + 1] = s2; bidx[u + 1] = gcol; }
                if (s3 < best[u + 1]) { best[u + 1] = s3; bidx[u + 1] = gcol + 1; }
            }
        }
    }

    // ---- Quad reduction (tig lanes hold different cols of same rows) ----
#pragma unroll
    for (int i = 0; i < 4; i++) {
#pragma unroll
        for (int off = 1; off <= 2; off <<= 1) {
            float v  = __shfl_xor_sync(0xffffffffu, best[i], off);
            int   ix = __shfl_xor_sync(0xffffffffu, bidx[i], off);
            if (v < best[i] || (v == best[i] && ix < bidx[i])) {
                best[i] = v; bidx[i] = ix;
            }
        }
    }

    // ---- Cross-warp combine: warps (wm, wn=0) and (wm, wn=32) share rows ---
    if (tig == 0) {
        int half = wn >> 5;   // 0 or 1
#pragma unroll
        for (int mb = 0; mb < 2; mb++)
#pragma unroll
            for (int h = 0; h < 2; h++) {
                int r = wm + mb * 16 + h * 8 + g;
                sRedV[r * 2 + half] = best[mb * 2 + h];
                sRedI[r * 2 + half] = bidx[mb * 2 + h];
            }
    }
    __syncthreads();
    if (tid < BM) {
        float v0 = sRedV[tid * 2],     v1 = sRedV[tid * 2 + 1];
        int   i0 = sRedI[tid * 2],     i1 = sRedI[tid * 2 + 1];
        int   win = (v1 < v0 || (v1 == v0 && i1 < i0)) ? i1 : i0;
        g_idx[(size_t)(bm0 + tid) * T_ + t] = win;
    }
}

// ---------------------------------------------------------------------------
// Kernel 3: gather winning codebook rows; append idxes (as float) if present.
// ---------------------------------------------------------------------------
__global__ void gather_kernel(const float* __restrict__ cb,
                              float* __restrict__ out, int write_idx) {
    int bt  = blockIdx.x;
    int t   = bt & (T_ - 1);
    int idx = g_idx[bt];
    const float4* src = (const float4*)(cb + ((size_t)t * K_ + idx) * D_);
    float4*       dst = (float4*)(out + (size_t)bt * D_);
    dst[threadIdx.x] = src[threadIdx.x];
    if (write_idx && threadIdx.x == 0)
        out[(size_t)B_ * T_ * D_ + bt] = (float)idx;
}

// ---------------------------------------------------------------------------
extern "C" void kernel_launch(void* const* d_in, const int* in_sizes, int n_in,
                              void* d_out, int out_size) {
    const float* x  = (const float*)d_in[0];   // [B, T, D] fp32
    const float* cb = (const float*)d_in[1];   // [T, K, D] fp32
    float* out = (float*)d_out;

    split_kernel<<<(T_ * K_) / 8, 256>>>(cb);

    cudaFuncSetAttribute(mma_kernel, cudaFuncAttributeMaxDynamicSharedMemorySize, SMEM_SZ);
    dim3 grid(B_ / BM, T_);
    mma_kernel<<<grid, 256, SMEM_SZ>>>(x);

    int write_idx = (out_size >= B_ * T_ * D_ + B_ * T_) ? 1 : 0;
    gather_kernel<<<B_ * T_, 64>>>(cb, out, write_idx);
}

// round 13
// speedup vs baseline: 2.3422x; 1.0311x over previous
#include <cuda_runtime.h>
#include <cuda_fp16.h>
#include <cstdint>

#define B_ 2048
#define T_ 32
#define K_ 1024
#define D_ 256
#define BM 128

// ---------------------------------------------------------------------------
// Scratch (static device arrays; no allocations allowed)
// ---------------------------------------------------------------------------
__device__ float  g_csq[T_ * K_];                // 0.5*||c||^2 (fp32 exact)
__device__ int    g_idx[B_ * T_];                // argmin indices
__device__ __half g_ch[(size_t)T_ * K_ * D_];    // codebook hi (fp16)
__device__ __half g_cl[(size_t)T_ * K_ * D_];    // codebook residual * 2048

// ---------------------------------------------------------------------------
// SMEM layout (bytes). Rows are 264 halfs = 528B; 132 words == 4 (mod 32):
// both scalar frag lanes and ldmatrix 8-row matrices are bank-conflict-free
// (row r starts at bank 4r, 4-word rows tile all 32 banks exactly once).
// ---------------------------------------------------------------------------
#define ASTR    528
#define AH_OFF  0
#define AL_OFF  67584
#define BH_OFF  135168
#define BL_OFF  168960
#define CSQ_OFF 202752
#define REDV_OFF 206848     // float sRedV[128][2]
#define REDI_OFF 207872     // int   sRedI[128][2]
#define SMEM_SZ  208896

__device__ __forceinline__ uint32_t smem_u32(const void* p) {
    uint32_t a;
    asm("{ .reg .u64 t; cvta.to.shared.u64 t, %1; cvt.u32.u64 %0, t; }" : "=r"(a) : "l"(p));
    return a;
}
__device__ __forceinline__ void ldsm4(uint32_t& r0, uint32_t& r1, uint32_t& r2,
                                      uint32_t& r3, uint32_t addr) {
    asm volatile("ldmatrix.sync.aligned.m8n8.x4.shared.b16 {%0,%1,%2,%3}, [%4];"
                 : "=r"(r0), "=r"(r1), "=r"(r2), "=r"(r3) : "r"(addr));
}
__device__ __forceinline__ void mma16816(float* c, const uint32_t* a, const uint32_t* b) {
    asm volatile("mma.sync.aligned.m16n8k16.row.col.f32.f16.f16.f32 "
                 "{%0,%1,%2,%3}, {%4,%5,%6,%7}, {%8,%9}, {%0,%1,%2,%3};"
                 : "+f"(c[0]), "+f"(c[1]), "+f"(c[2]), "+f"(c[3])
                 : "r"(a[0]), "r"(a[1]), "r"(a[2]), "r"(a[3]), "r"(b[0]), "r"(b[1]));
}

// ---------------------------------------------------------------------------
// Kernel 1: codebook split (fp16 hi + 2048*residual) + 0.5*||c||^2. Warp/row.
// ---------------------------------------------------------------------------
__global__ void split_kernel(const float* __restrict__ cb) {
    int row  = blockIdx.x * 8 + (threadIdx.x >> 5);
    int lane = threadIdx.x & 31;
    const float4* p = (const float4*)(cb + (size_t)row * D_);
    float4 v0 = p[lane * 2 + 0];
    float4 v1 = p[lane * 2 + 1];
    float a[8] = {v0.x, v0.y, v0.z, v0.w, v1.x, v1.y, v1.z, v1.w};
    float s = 0.f;
#pragma unroll
    for (int i = 0; i < 8; i++) s += a[i] * a[i];
#pragma unroll
    for (int o = 16; o > 0; o >>= 1) s += __shfl_xor_sync(0xffffffffu, s, o);
    if (lane == 0) g_csq[row] = 0.5f * s;

    __half h[8], l[8];
#pragma unroll
    for (int i = 0; i < 8; i++) {
        h[i] = __float2half_rn(a[i]);
        l[i] = __float2half_rn((a[i] - __half2float(h[i])) * 2048.f);
    }
    uint4 uh, ul;
    uh.x = ((uint32_t)__half_as_ushort(h[0])) | ((uint32_t)__half_as_ushort(h[1]) << 16);
    uh.y = ((uint32_t)__half_as_ushort(h[2])) | ((uint32_t)__half_as_ushort(h[3]) << 16);
    uh.z = ((uint32_t)__half_as_ushort(h[4])) | ((uint32_t)__half_as_ushort(h[5]) << 16);
    uh.w = ((uint32_t)__half_as_ushort(h[6])) | ((uint32_t)__half_as_ushort(h[7]) << 16);
    ul.x = ((uint32_t)__half_as_ushort(l[0])) | ((uint32_t)__half_as_ushort(l[1]) << 16);
    ul.y = ((uint32_t)__half_as_ushort(l[2])) | ((uint32_t)__half_as_ushort(l[3]) << 16);
    ul.z = ((uint32_t)__half_as_ushort(l[4])) | ((uint32_t)__half_as_ushort(l[5]) << 16);
    ul.w = ((uint32_t)__half_as_ushort(l[6])) | ((uint32_t)__half_as_ushort(l[7]) << 16);
    *(uint4*)(g_ch + (size_t)row * D_ + lane * 8) = uh;
    *(uint4*)(g_cl + (size_t)row * D_ + lane * 8) = ul;
}

// ---------------------------------------------------------------------------
// Kernel 2: HMMA split-fp16 GEMM + fused argmin, 3-MMA form, ldmatrix.x4
// fragment loads (8 ldmatrix vs 32 LDS.32 per warp-k-step; same math as the
// 418us scalar-load version). Cross-warp argmin via SMEM.
// ---------------------------------------------------------------------------
__global__ __launch_bounds__(256, 1)
void mma_kernel(const float* __restrict__ x) {
    extern __shared__ char smem[];
    const int tid  = threadIdx.x;
    const int lane = tid & 31;
    const int wid  = tid >> 5;
    const int t    = blockIdx.y;
    const int bm0  = blockIdx.x * BM;
    const int wm   = (wid >> 1) * 32;   // warp row offset in CTA tile
    const int wn   = (wid & 1) * 32;    // warp col offset in 64-wide n-tile
    const int g    = lane >> 2;         // groupID (fragment row / B col)
    const int tig  = lane & 3;          // thread-in-group (k pairs)
    const uint32_t sb = smem_u32(smem);
    float* sCsq  = (float*)(smem + CSQ_OFF);
    float* sRedV = (float*)(smem + REDV_OFF);
    int*   sRedI = (int*)(smem + REDI_OFF);

    // ---- Prologue: stage x tile split to (hi, lo*2048) fp16; preload csq --
#pragma unroll
    for (int it = 0; it < 32; it++) {
        int q   = tid + it * 256;          // 8192 float4 loads
        int row = q >> 6;
        int c4  = q & 63;
        float4 v = *(const float4*)(x + ((size_t)(bm0 + row) * T_ + t) * D_ + c4 * 4);
        float a4[4] = {v.x, v.y, v.z, v.w};
        __half h4[4], l4[4];
#pragma unroll
        for (int i = 0; i < 4; i++) {
            h4[i] = __float2half_rn(a4[i]);
            l4[i] = __float2half_rn((a4[i] - __half2float(h4[i])) * 2048.f);
        }
        uint2 uh, ul;
        uh.x = ((uint32_t)__half_as_ushort(h4[0])) | ((uint32_t)__half_as_ushort(h4[1]) << 16);
        uh.y = ((uint32_t)__half_as_ushort(h4[2])) | ((uint32_t)__half_as_ushort(h4[3]) << 16);
        ul.x = ((uint32_t)__half_as_ushort(l4[0])) | ((uint32_t)__half_as_ushort(l4[1]) << 16);
        ul.y = ((uint32_t)__half_as_ushort(l4[2])) | ((uint32_t)__half_as_ushort(l4[3]) << 16);
        *(uint2*)(smem + AH_OFF + row * ASTR + c4 * 8) = uh;
        *(uint2*)(smem + AL_OFF + row * ASTR + c4 * 8) = ul;
    }
#pragma unroll
    for (int i = 0; i < 4; i++) sCsq[tid + i * 256] = g_csq[t * K_ + tid + i * 256];

    // ldmatrix per-lane base offsets (bytes within each A/B array).
    // A x4: lanes 0-15 -> rows wm+0..15 @ kk; lanes 16-31 -> same rows @ kk+8
    //   => r0=a0(rows 0-7,k) r1=a1(rows 8-15,k) r2=a2(k+8) r3=a3(k+8)
    const uint32_t aOff = (uint32_t)(wm + (lane & 15)) * ASTR + ((uint32_t)(lane >> 4) << 4);
    // B x4: lanes 0-7 -> n wn+0..7 @ k; 8-15 -> same n @ k+8; 16-23 -> n+8 @ k;
    // 24-31 -> n+8 @ k+8  => r0=b0(oct0) r1=b1(oct0) r2=b0(oct1) r3=b1(oct1)
    const uint32_t bOff = (uint32_t)(wn + (lane & 7) + ((lane >> 4) << 3)) * ASTR
                        + (((uint32_t)(lane >> 3) & 1) << 4);

    float best[4];
    int   bidx[4];
#pragma unroll
    for (int i = 0; i < 4; i++) { best[i] = 3.4e38f; bidx[i] = 0; }

    const float inv = 1.f / 2048.f;

    for (int nt = 0; nt < 16; nt++) {
        const int n0 = nt * 64;
        __syncthreads();   // prev k-loop done (B reuse) / prologue done (nt=0)

        // ---- Load B tile: 64 codes x 256 d, hi + lo ----
#pragma unroll
        for (int it = 0; it < 16; it++) {
            int q   = tid + it * 256;       // 4096 uint4
            int arr = q >> 11;
            int e   = q & 2047;
            int n   = e >> 5;
            int ck  = e & 31;
            const __half* src = (arr ? g_cl : g_ch)
                              + ((size_t)t * K_ + n0 + n) * D_ + ck * 8;
            *(uint4*)(smem + (arr ? BL_OFF : BH_OFF) + n * ASTR + ck * 16) =
                *(const uint4*)src;
        }
        __syncthreads();

        // ---- K-loop: C1 = xh*ch ; C2 = xh*cl + xl*ch ----
        float C1[2][4][4], C2[2][4][4];
#pragma unroll
        for (int mb = 0; mb < 2; mb++)
#pragma unroll
            for (int nb = 0; nb < 4; nb++)
#pragma unroll
                for (int r = 0; r < 4; r++) { C1[mb][nb][r] = 0.f; C2[mb][nb][r] = 0.f; }

#pragma unroll 2
        for (int kk = 0; kk < D_; kk += 16) {
            uint32_t ah[2][4], al[2][4], bh[4][2], bl[4][2];
#pragma unroll
            for (int mb = 0; mb < 2; mb++) {
                uint32_t a = aOff + (uint32_t)mb * (16 * ASTR) + (uint32_t)kk * 2;
                ldsm4(ah[mb][0], ah[mb][1], ah[mb][2], ah[mb][3], sb + AH_OFF + a);
                ldsm4(al[mb][0], al[mb][1], al[mb][2], al[mb][3], sb + AL_OFF + a);
            }
#pragma unroll
            for (int nb2 = 0; nb2 < 2; nb2++) {
                uint32_t b = bOff + (uint32_t)nb2 * (16 * ASTR) + (uint32_t)kk * 2;
                ldsm4(bh[nb2*2][0], bh[nb2*2][1], bh[nb2*2+1][0], bh[nb2*2+1][1],
                      sb + BH_OFF + b);
                ldsm4(bl[nb2*2][0], bl[nb2*2][1], bl[nb2*2+1][0], bl[nb2*2+1][1],
                      sb + BL_OFF + b);
            }
#pragma unroll
            for (int mb = 0; mb < 2; mb++)
#pragma unroll
                for (int nb = 0; nb < 4; nb++) {
                    mma16816(C1[mb][nb], ah[mb], bh[nb]);
                    mma16816(C2[mb][nb], ah[mb], bl[nb]);
                    mma16816(C2[mb][nb], al[mb], bh[nb]);
                }
        }

        // ---- Fused argmin over this tile (registers + smem csq) ----
        // C frag: c0:(g, c) c1:(g, c+1) c2:(g+8, c) c3:(g+8, c+1), c = tig*2.
#pragma unroll
        for (int nb = 0; nb < 4; nb++) {
            int gcol = n0 + wn + nb * 8 + tig * 2;
            float cs0 = sCsq[gcol];
            float cs1 = sCsq[gcol + 1];
#pragma unroll
            for (int mb = 0; mb < 2; mb++) {
                float s0 = cs0 - (C1[mb][nb][0] + C2[mb][nb][0] * inv);
                float s1 = cs1 - (C1[mb][nb][1] + C2[mb][nb][1] * inv);
                float s2 = cs0 - (C1[mb][nb][2] + C2[mb][nb][2] * inv);
                float s3 = cs1 - (C1[mb][nb][3] + C2[mb][nb][3] * inv);
                int u = mb * 2;
                if (s0 < best[u])     { best[u]     = s0; bidx[u]     = gcol; }
                if (s1 < best[u])     { best[u]     = s1; bidx[u]     = gcol + 1; }
                if (s2 < best[u + 1]) { best[u + 1] = s2; bidx[u + 1] = gcol; }
                if (s3 < best[u + 1]) { best[u + 1] = s3; bidx[u + 1] = gcol + 1; }
            }
        }
    }

    // ---- Quad reduction (tig lanes hold different cols of same rows) ----
#pragma unroll
    for (int i = 0; i < 4; i++) {
#pragma unroll
        for (int off = 1; off <= 2; off <<= 1) {
            float v  = __shfl_xor_sync(0xffffffffu, best[i], off);
            int   ix = __shfl_xor_sync(0xffffffffu, bidx[i], off);
            if (v < best[i] || (v == best[i] && ix < bidx[i])) {
                best[i] = v; bidx[i] = ix;
            }
        }
    }

    // ---- Cross-warp combine: warps (wm, wn=0) and (wm, wn=32) share rows ---
    if (tig == 0) {
        int half = wn >> 5;   // 0 or 1
#pragma unroll
        for (int mb = 0; mb < 2; mb++)
#pragma unroll
            for (int h = 0; h < 2; h++) {
                int r = wm + mb * 16 + h * 8 + g;
                sRedV[r * 2 + half] = best[mb * 2 + h];
                sRedI[r * 2 + half] = bidx[mb * 2 + h];
            }
    }
    __syncthreads();
    if (tid < BM) {
        float v0 = sRedV[tid * 2],     v1 = sRedV[tid * 2 + 1];
        int   i0 = sRedI[tid * 2],     i1 = sRedI[tid * 2 + 1];
        int   win = (v1 < v0 || (v1 == v0 && i1 < i0)) ? i1 : i0;
        g_idx[(size_t)(bm0 + tid) * T_ + t] = win;
    }
}

// ---------------------------------------------------------------------------
// Kernel 3: gather winning codebook rows; append idxes (as float) if present.
// ---------------------------------------------------------------------------
__global__ void gather_kernel(const float* __restrict__ cb,
                              float* __restrict__ out, int write_idx) {
    int bt  = blockIdx.x;
    int t   = bt & (T_ - 1);
    int idx = g_idx[bt];
    const float4* src = (const float4*)(cb + ((size_t)t * K_ + idx) * D_);
    float4*       dst = (float4*)(out + (size_t)bt * D_);
    dst[threadIdx.x] = src[threadIdx.x];
    if (write_idx && threadIdx.x == 0)
        out[(size_t)B_ * T_ * D_ + bt] = (float)idx;
}

// ---------------------------------------------------------------------------
extern "C" void kernel_launch(void* const* d_in, const int* in_sizes, int n_in,
                              void* d_out, int out_size) {
    const float* x  = (const float*)d_in[0];   // [B, T, D] fp32
    const float* cb = (const float*)d_in[1];   // [T, K, D] fp32
    float* out = (float*)d_out;

    split_kernel<<<(T_ * K_) / 8, 256>>>(cb);

    cudaFuncSetAttribute(mma_kernel, cudaFuncAttributeMaxDynamicSharedMemorySize, SMEM_SZ);
    dim3 grid(B_ / BM, T_);
    mma_kernel<<<grid, 256, SMEM_SZ>>>(x);

    int write_idx = (out_size >= B_ * T_ * D_ + B_ * T_) ? 1 : 0;
    gather_kernel<<<B_ * T_, 64>>>(cb, out, write_idx);
}